// round 12
// baseline (speedup 1.0000x reference)
#include <cuda_runtime.h>
#include <cuda_bf16.h>

// LigerJSD: generalized JSD with beta=0.5 on log-prob inputs p, q (fp32).
// loss = sum( 0.5*P*(p - log_m) + 0.5*Q*(q - log_m) ) / n_rows
// where P=exp(p), Q=exp(q), log_m = log(0.5*(P+Q)).
//
// HBM-bound streaming reduction: 1.049 GB in, 4 bytes out.
// FINAL SHAPE (measured optimum over R3-R11): 4-deep unroll with
// interleaved p/q __ldcs loads, occ 8 (regs=32), fused last-block-done
// epilogue. Timed 152.7/153.0/153.4 us across three holds (~6.9 TB/s,
// ~87% of HBM spec ~= LTS path ceiling). All tested alternatives regressed:
// 2-deep plain (158.2), occ-6 (168.8), stream-grouped + algebraic (156.4).

#define THREADS 256
#define BLOCKS  1184   // 148 SMs * 8 CTAs — exactly one wave

__device__ float        g_partials[BLOCKS];
__device__ unsigned int g_ticket = 0;   // self-resetting; ok for graph replay

__device__ __forceinline__ float jsd_elem(float p, float q) {
    float P = __expf(p);
    float Q = __expf(q);
    float m = 0.5f * (P + Q);
    float lm = __logf(m);
    return 0.5f * (P * (p - lm) + Q * (q - lm));
}

__device__ __forceinline__ float jsd4(float4 a, float4 b) {
    return jsd_elem(a.x, b.x) + jsd_elem(a.y, b.y)
         + jsd_elem(a.z, b.z) + jsd_elem(a.w, b.w);
}

// Full block reduce; result valid in thread 0.
__device__ __forceinline__ float block_reduce(float v) {
    __shared__ float s[THREADS / 32];
    #pragma unroll
    for (int off = 16; off > 0; off >>= 1)
        v += __shfl_down_sync(0xFFFFFFFFu, v, off);
    int lane = threadIdx.x & 31;
    int wid  = threadIdx.x >> 5;
    if (lane == 0) s[wid] = v;
    __syncthreads();
    if (wid == 0) {
        v = (lane < THREADS / 32) ? s[lane] : 0.0f;
        #pragma unroll
        for (int off = 16; off > 0; off >>= 1)
            v += __shfl_down_sync(0xFFFFFFFFu, v, off);
    }
    return v;
}

__global__ void __launch_bounds__(THREADS, 8)
jsd_fused_kernel(const float4* __restrict__ p4,
                 const float4* __restrict__ q4,
                 const float*  __restrict__ p,
                 const float*  __restrict__ q,
                 float* __restrict__ out,
                 int n4, int n_tail_start, int n_total, float inv_rows) {
    float acc = 0.0f;
    const int stride = gridDim.x * blockDim.x;
    int i = blockIdx.x * blockDim.x + threadIdx.x;

    // 4-deep unroll: 8 concurrent 16B streaming loads per iteration.
    for (; i + 3 * stride < n4; i += 4 * stride) {
        float4 pa = __ldcs(p4 + i);
        float4 qa = __ldcs(q4 + i);
        float4 pb = __ldcs(p4 + i + stride);
        float4 qb = __ldcs(q4 + i + stride);
        float4 pc = __ldcs(p4 + i + 2 * stride);
        float4 qc = __ldcs(q4 + i + 2 * stride);
        float4 pd = __ldcs(p4 + i + 3 * stride);
        float4 qd = __ldcs(q4 + i + 3 * stride);
        acc += jsd4(pa, qa) + jsd4(pb, qb) + jsd4(pc, qc) + jsd4(pd, qd);
    }
    for (; i < n4; i += stride)
        acc += jsd4(__ldcs(p4 + i), __ldcs(q4 + i));

    // scalar tail (n % 4 != 0) — empty for this shape but safe
    if (blockIdx.x == 0)
        for (int t = n_tail_start + threadIdx.x; t < n_total; t += THREADS)
            acc += jsd_elem(p[t], q[t]);

    float bsum = block_reduce(acc);

    // Last-block-done final reduction (deterministic order).
    __shared__ unsigned int s_is_last;
    if (threadIdx.x == 0) {
        g_partials[blockIdx.x] = bsum;
        __threadfence();
        unsigned int t = atomicAdd(&g_ticket, 1u);
        s_is_last = (t == (unsigned int)(gridDim.x - 1)) ? 1u : 0u;
    }
    __syncthreads();

    if (s_is_last) {
        float v = 0.0f;
        for (int k = threadIdx.x; k < BLOCKS; k += THREADS)
            v += g_partials[k];
        float total = block_reduce(v);
        if (threadIdx.x == 0) {
            out[0] = total * inv_rows;
            g_ticket = 0;   // reset for next graph replay
        }
    }
}

extern "C" void kernel_launch(void* const* d_in, const int* in_sizes, int n_in,
                              void* d_out, int out_size) {
    const float* p = (const float*)d_in[0];
    const float* q = (const float*)d_in[1];
    float* out = (float*)d_out;

    int n = in_sizes[0];          // 4096*32000 = 131,072,000
    int n4 = n / 4;
    int tail_start = n4 * 4;
    const int B_rows = 4096;      // loss divided by n_rows
    float inv_rows = 1.0f / (float)B_rows;

    jsd_fused_kernel<<<BLOCKS, THREADS>>>((const float4*)p, (const float4*)q,
                                          p, q, out,
                                          n4, tail_start, n, inv_rows);
}

// round 13
// speedup vs baseline: 1.0139x; 1.0139x over previous
#include <cuda_runtime.h>
#include <cuda_bf16.h>

// LigerJSD: generalized JSD with beta=0.5 on log-prob inputs p, q (fp32).
// loss = sum( 0.5*P*(p - log_m) + 0.5*Q*(q - log_m) ) / n_rows
// where P=exp(p), Q=exp(q), log_m = log(0.5*(P+Q)).
//
// HBM-bound streaming reduction: 1.049 GB in, 4 bytes out.
// FINAL SHAPE (measured optimum over R3-R12): 4-deep unroll with
// interleaved p/q __ldcs loads, occ 8 (regs=32), fused last-block-done
// epilogue. Timed 152.7/153.0/153.4/153.6 us across four holds at
// ~6.93 TB/s — equal to the B300 chip-level LTS throughput cap
// (~6300 B/cyc, path-independent: LDG.cv == TMA), i.e. the hardware
// ceiling for any global-read path. All tested alternatives regressed:
// 2-deep plain (158.2), occ-6 (168.8), stream-grouped + algebraic (156.4),
// separate final kernel (156.4).

#define THREADS 256
#define BLOCKS  1184   // 148 SMs * 8 CTAs — exactly one wave

__device__ float        g_partials[BLOCKS];
__device__ unsigned int g_ticket = 0;   // self-resetting; ok for graph replay

__device__ __forceinline__ float jsd_elem(float p, float q) {
    float P = __expf(p);
    float Q = __expf(q);
    float m = 0.5f * (P + Q);
    float lm = __logf(m);
    return 0.5f * (P * (p - lm) + Q * (q - lm));
}

__device__ __forceinline__ float jsd4(float4 a, float4 b) {
    return jsd_elem(a.x, b.x) + jsd_elem(a.y, b.y)
         + jsd_elem(a.z, b.z) + jsd_elem(a.w, b.w);
}

// Full block reduce; result valid in thread 0.
__device__ __forceinline__ float block_reduce(float v) {
    __shared__ float s[THREADS / 32];
    #pragma unroll
    for (int off = 16; off > 0; off >>= 1)
        v += __shfl_down_sync(0xFFFFFFFFu, v, off);
    int lane = threadIdx.x & 31;
    int wid  = threadIdx.x >> 5;
    if (lane == 0) s[wid] = v;
    __syncthreads();
    if (wid == 0) {
        v = (lane < THREADS / 32) ? s[lane] : 0.0f;
        #pragma unroll
        for (int off = 16; off > 0; off >>= 1)
            v += __shfl_down_sync(0xFFFFFFFFu, v, off);
    }
    return v;
}

__global__ void __launch_bounds__(THREADS, 8)
jsd_fused_kernel(const float4* __restrict__ p4,
                 const float4* __restrict__ q4,
                 const float*  __restrict__ p,
                 const float*  __restrict__ q,
                 float* __restrict__ out,
                 int n4, int n_tail_start, int n_total, float inv_rows) {
    float acc = 0.0f;
    const int stride = gridDim.x * blockDim.x;
    int i = blockIdx.x * blockDim.x + threadIdx.x;

    // 4-deep unroll: 8 concurrent 16B streaming loads per iteration.
    for (; i + 3 * stride < n4; i += 4 * stride) {
        float4 pa = __ldcs(p4 + i);
        float4 qa = __ldcs(q4 + i);
        float4 pb = __ldcs(p4 + i + stride);
        float4 qb = __ldcs(q4 + i + stride);
        float4 pc = __ldcs(p4 + i + 2 * stride);
        float4 qc = __ldcs(q4 + i + 2 * stride);
        float4 pd = __ldcs(p4 + i + 3 * stride);
        float4 qd = __ldcs(q4 + i + 3 * stride);
        acc += jsd4(pa, qa) + jsd4(pb, qb) + jsd4(pc, qc) + jsd4(pd, qd);
    }
    for (; i < n4; i += stride)
        acc += jsd4(__ldcs(p4 + i), __ldcs(q4 + i));

    // scalar tail (n % 4 != 0) — empty for this shape but safe
    if (blockIdx.x == 0)
        for (int t = n_tail_start + threadIdx.x; t < n_total; t += THREADS)
            acc += jsd_elem(p[t], q[t]);

    float bsum = block_reduce(acc);

    // Last-block-done final reduction (deterministic order).
    __shared__ unsigned int s_is_last;
    if (threadIdx.x == 0) {
        g_partials[blockIdx.x] = bsum;
        __threadfence();
        unsigned int t = atomicAdd(&g_ticket, 1u);
        s_is_last = (t == (unsigned int)(gridDim.x - 1)) ? 1u : 0u;
    }
    __syncthreads();

    if (s_is_last) {
        float v = 0.0f;
        for (int k = threadIdx.x; k < BLOCKS; k += THREADS)
            v += g_partials[k];
        float total = block_reduce(v);
        if (threadIdx.x == 0) {
            out[0] = total * inv_rows;
            g_ticket = 0;   // reset for next graph replay
        }
    }
}

extern "C" void kernel_launch(void* const* d_in, const int* in_sizes, int n_in,
                              void* d_out, int out_size) {
    const float* p = (const float*)d_in[0];
    const float* q = (const float*)d_in[1];
    float* out = (float*)d_out;

    int n = in_sizes[0];          // 4096*32000 = 131,072,000
    int n4 = n / 4;
    int tail_start = n4 * 4;
    const int B_rows = 4096;      // loss divided by n_rows
    float inv_rows = 1.0f / (float)B_rows;

    jsd_fused_kernel<<<BLOCKS, THREADS>>>((const float4*)p, (const float4*)q,
                                          p, q, out,
                                          n4, tail_start, n, inv_rows);
}